// round 4
// baseline (speedup 1.0000x reference)
#include <cuda_runtime.h>
#include <cuda_bf16.h>
#include <mma.h>
#include <math.h>

using namespace nvcuda;

#define NTOK 8192
#define CDIM 256
#define NHEAD 4
#define QKVN 768
#define MAXDIST 4.242640687119285f  /* sqrt(18) */

// ---------------- scratch ----------------
__device__ float g_qkv[NTOK * QKVN];              // silu(x@W_qkv) float (q|k|v)
__device__ float g_q[NTOK * CDIM];
__device__ float g_k[NTOK * CDIM];
__device__ float g_att[NTOK * CDIM];
__device__ float g_width[NTOK * NHEAD];
__device__ float g_sharp[NTOK * NHEAD];
__device__ float g_rmsinv[NTOK];

// split operands: per-row [hi(256) | lo(256)], stride 512
__device__ __nv_bfloat16 g_xsplit[NTOK * 512];
__device__ __nv_bfloat16 g_vsplit[NTOK * 512];
__device__ __nv_bfloat16 g_msplit[NTOK * 512];
// weight splits (separate hi / lo, row-major 256 x N)
__device__ __nv_bfloat16 g_wqkv_hi[256 * 768], g_wqkv_lo[256 * 768];
__device__ __nv_bfloat16 g_wgate_hi[256 * 256], g_wgate_lo[256 * 256];
__device__ __nv_bfloat16 g_wout_hi[256 * 256],  g_wout_lo[256 * 256];

__device__ __forceinline__ float sigmoidf_(float x) { return 1.f / (1.f + __expf(-x)); }
__device__ __forceinline__ float siluf_(float x) { return x * sigmoidf_(x); }
__device__ __forceinline__ void split_bf16(float f, __nv_bfloat16& hi, __nv_bfloat16& lo) {
    hi = __float2bfloat16(f);
    lo = __float2bfloat16(f - __bfloat162float(hi));
}

__device__ __forceinline__ void cp_async16(void* smem, const void* gmem) {
    unsigned s = (unsigned)__cvta_generic_to_shared(smem);
    asm volatile("cp.async.cg.shared.global [%0], [%1], 16;" :: "r"(s), "l"(gmem));
}
__device__ __forceinline__ void cp_commit() { asm volatile("cp.async.commit_group;"); }
template <int N> __device__ __forceinline__ void cp_wait() {
    asm volatile("cp.async.wait_group %0;" :: "n"(N));
}

// ---------------- split kernels ----------------
__global__ void __launch_bounds__(256) split_x_kernel(const float* __restrict__ x)
{
    int i = blockIdx.x * 256 + threadIdx.x;           // float4 index, 524288 total
    int r = i >> 6;
    int c = (i & 63) * 4;
    float4 v = ((const float4*)x)[i];
    float e[4] = {v.x, v.y, v.z, v.w};
#pragma unroll
    for (int q = 0; q < 4; q++) {
        __nv_bfloat16 hi, lo;
        split_bf16(e[q], hi, lo);
        g_xsplit[(size_t)r * 512 + c + q] = hi;
        g_xsplit[(size_t)r * 512 + 256 + c + q] = lo;
    }
}

__global__ void __launch_bounds__(256) split_w_kernel(
    const float* __restrict__ Wqkv, const float* __restrict__ Wgate,
    const float* __restrict__ Wout)
{
    int i = blockIdx.x * 256 + threadIdx.x;  // float4 idx: 49152 + 16384 + 16384
    const float* src; __nv_bfloat16 *hi, *lo; int off;
    if (i < 49152)      { src = Wqkv;  hi = g_wqkv_hi;  lo = g_wqkv_lo;  off = i; }
    else if (i < 65536) { src = Wgate; hi = g_wgate_hi; lo = g_wgate_lo; off = i - 49152; }
    else                { src = Wout;  hi = g_wout_hi;  lo = g_wout_lo;  off = i - 65536; }
    float4 v = ((const float4*)src)[off];
    float e[4] = {v.x, v.y, v.z, v.w};
#pragma unroll
    for (int q = 0; q < 4; q++) {
        __nv_bfloat16 h, l;
        split_bf16(e[q], h, l);
        hi[off * 4 + q] = h;
        lo[off * 4 + q] = l;
    }
}

// ---------------- pipelined bf16 GEMM, K'=768 (3-segment split product) ----------------
// A: split rows [hi|lo] stride 512.  B: hi/lo arrays 256 x ldb.
// segments: seg0 A_hi*B_hi, seg1 A_lo*B_hi, seg2 A_hi*B_lo.
// block tile 128x64, KT=32, 8 warps (4x2), warp tile 32x32, double-buffered cp.async.
// EPI 0: silu -> Cmat                                   (out GEMM)
// EPI 1: gate-merge -> g_msplit hi/lo                   (gate GEMM)
// EPI 2: silu -> Cmat(float qkv) + v-split for c>=512   (qkv GEMM)
#define A_LD 40
#define B_LD 72
#define C_LD 36

template <int EPI>
__global__ void __launch_bounds__(256) gemm_bf16(
    const __nv_bfloat16* __restrict__ Asp,
    const __nv_bfloat16* __restrict__ Bhi,
    const __nv_bfloat16* __restrict__ Blo, int ldb,
    float* __restrict__ Cmat, int ldc,
    const float* __restrict__ Afull, int ldaf,
    const float* __restrict__ bias,
    const float* __restrict__ wonorm)
{
    __shared__ __align__(16) unsigned char smraw[36864];
    __nv_bfloat16 (*As)[128][A_LD] = (__nv_bfloat16(*)[128][A_LD])smraw;           // 2 bufs
    __nv_bfloat16 (*Bs)[32][B_LD]  = (__nv_bfloat16(*)[32][B_LD])(smraw + 20480);
    float (*Cs)[32][C_LD]          = (float(*)[32][C_LD])smraw;

    int tid = threadIdx.x;
    int warp = tid >> 5, lane = tid & 31;
    int wm = warp >> 1, wn = warp & 1;
    int rowBase = blockIdx.y * 128;
    int colBase = blockIdx.x * 64;

    // A chunks: 2 per thread. chunk c: row=c>>2, col8=(c&3)*8
    int a_r0 = tid >> 2, a_c8 = (tid & 3) * 8;
    // B chunks: 1 per thread. row=tid>>3, col8=(tid&7)*8
    int b_r = tid >> 3, b_c8 = (tid & 7) * 8;

    auto load_tile = [&](int kt, int buf) {
        int seg = kt >> 3;
        int krem = (kt & 7) * 32;
        int aoff = (seg == 1) ? 256 : 0;
        const __nv_bfloat16* Ag = Asp + (size_t)(rowBase) * 512 + aoff + krem;
        cp_async16(&As[buf][a_r0][a_c8],      Ag + (size_t)a_r0 * 512 + a_c8);
        cp_async16(&As[buf][a_r0 + 64][a_c8], Ag + (size_t)(a_r0 + 64) * 512 + a_c8);
        const __nv_bfloat16* Bg = ((seg == 2) ? Blo : Bhi) + (size_t)krem * ldb + colBase;
        cp_async16(&Bs[buf][b_r][b_c8], Bg + (size_t)b_r * ldb + b_c8);
    };

    wmma::fragment<wmma::accumulator, 16, 16, 16, float> cf[2][2];
#pragma unroll
    for (int i = 0; i < 2; i++)
#pragma unroll
        for (int j = 0; j < 2; j++) wmma::fill_fragment(cf[i][j], 0.f);

    load_tile(0, 0);
    cp_commit();

    for (int kt = 0; kt < 24; kt++) {
        int buf = kt & 1;
        if (kt + 1 < 24) {
            load_tile(kt + 1, buf ^ 1);
            cp_commit();
            cp_wait<1>();
        } else {
            cp_wait<0>();
        }
        __syncthreads();
#pragma unroll
        for (int ks = 0; ks < 32; ks += 16) {
            wmma::fragment<wmma::matrix_a, 16, 16, 16, __nv_bfloat16, wmma::row_major> af[2];
            wmma::fragment<wmma::matrix_b, 16, 16, 16, __nv_bfloat16, wmma::row_major> bf[2];
#pragma unroll
            for (int i = 0; i < 2; i++)
                wmma::load_matrix_sync(af[i], &As[buf][wm * 32 + i * 16][ks], A_LD);
#pragma unroll
            for (int j = 0; j < 2; j++)
                wmma::load_matrix_sync(bf[j], &Bs[buf][ks][wn * 32 + j * 16], B_LD);
#pragma unroll
            for (int i = 0; i < 2; i++)
#pragma unroll
                for (int j = 0; j < 2; j++)
                    wmma::mma_sync(cf[i][j], af[i], bf[j], cf[i][j]);
        }
        __syncthreads();
    }

    // epilogue via smem roundtrip (Cs aliases As/Bs; sync above protects)
#pragma unroll
    for (int i = 0; i < 2; i++)
#pragma unroll
        for (int j = 0; j < 2; j++)
            wmma::store_matrix_sync(&Cs[warp][i * 16][j * 16], cf[i][j], C_LD, wmma::mem_row_major);
    __syncwarp();

#pragma unroll 4
    for (int rr = 0; rr < 32; rr++) {
        int r = rowBase + wm * 32 + rr;
        int c = colBase + wn * 32 + lane;
        float val = Cs[warp][rr][lane];
        if (EPI == 0) {
            Cmat[(size_t)r * ldc + c] = siluf_(val);
        } else if (EPI == 2) {
            float s = siluf_(val);
            Cmat[(size_t)r * ldc + c] = s;
            if (c >= 512) {
                __nv_bfloat16 hi, lo;
                split_bf16(s, hi, lo);
                g_vsplit[(size_t)r * 512 + (c - 512)] = hi;
                g_vsplit[(size_t)r * 512 + 256 + (c - 512)] = lo;
            }
        } else {
            float t = val + bias[c];
            float g = sigmoidf_(siluf_(t));
            float vv = Afull[(size_t)r * ldaf + c];
            float att = g_att[(size_t)r * CDIM + c] * g_rmsinv[r] * wonorm[c];
            float merged = g * vv + (1.f - g) * att;
            __nv_bfloat16 hi, lo;
            split_bf16(merged, hi, lo);
            g_msplit[(size_t)r * 512 + c] = hi;
            g_msplit[(size_t)r * 512 + 256 + c] = lo;
        }
    }
}

// ---------------- fused rmsnorm + RoPE (pos = head index!) + width/sharp ----------------
__global__ void __launch_bounds__(256) norm_rope_wp(
    const float* __restrict__ x,
    const float* __restrict__ Wwp, const float* __restrict__ bwp,
    const float* __restrict__ wqn, const float* __restrict__ wkn)
{
    int lane = threadIdx.x & 31;
    int tok = blockIdx.x * 8 + (threadIdx.x >> 5);
    const float* row = g_qkv + (size_t)tok * QKVN;

    float qv[8], kv[8];
#pragma unroll
    for (int e = 0; e < 8; e++) {
        qv[e] = row[lane * 8 + e];
        kv[e] = row[256 + lane * 8 + e];
    }
    float sq = 0.f, sk = 0.f;
#pragma unroll
    for (int e = 0; e < 8; e++) { sq += qv[e] * qv[e]; sk += kv[e] * kv[e]; }
#pragma unroll
    for (int off = 1; off < 8; off <<= 1) {
        sq += __shfl_xor_sync(0xffffffffu, sq, off);
        sk += __shfl_xor_sync(0xffffffffu, sk, off);
    }
    float rq = rsqrtf(sq * (1.f / 64.f) + 1e-6f);
    float rk = rsqrtf(sk * (1.f / 64.f) + 1e-6f);

    int h = lane >> 3;
    int dl = lane & 7;
#pragma unroll
    for (int e = 0; e < 8; e++) {
        int d = dl * 8 + e;
        qv[e] *= rq * wqn[d];
        kv[e] *= rk * wkn[d];
    }
    float sgn = (lane & 4) ? 1.f : -1.f;
#pragma unroll
    for (int e = 0; e < 8; e++) {
        float qp = __shfl_xor_sync(0xffffffffu, qv[e], 4);
        float kp = __shfl_xor_sync(0xffffffffu, kv[e], 4);
        int f = (lane & 3) * 8 + e;
        float freq = exp2f(-(float)f * (13.287712379549449f / 32.f));
        float ang = (float)h * freq;
        float ss, cc;
        __sincosf(ang, &ss, &cc);
        qv[e] = qv[e] * cc + sgn * qp * ss;
        kv[e] = kv[e] * cc + sgn * kp * ss;
    }
#pragma unroll
    for (int e = 0; e < 8; e++) {
        g_q[(size_t)tok * CDIM + lane * 8 + e] = qv[e];
        g_k[(size_t)tok * CDIM + lane * 8 + e] = kv[e];
    }

    const float* xr = x + (size_t)tok * CDIM;
    float xe[8];
#pragma unroll
    for (int e = 0; e < 8; e++) xe[e] = xr[lane * 8 + e];
    float outv[8];
#pragma unroll
    for (int o = 0; o < 8; o++) {
        float p = 0.f;
#pragma unroll
        for (int e = 0; e < 8; e++) p += xe[e] * Wwp[(lane * 8 + e) * 8 + o];
#pragma unroll
        for (int off = 16; off >= 1; off >>= 1) p += __shfl_xor_sync(0xffffffffu, p, off);
        outv[o] = p;
    }
    if (lane < 8) {
        float w = siluf_(outv[lane] + bwp[lane]);
        if (lane < 4) g_width[tok * 4 + lane] = sigmoidf_(w) * MAXDIST + 0.5f;
        else          g_sharp[tok * 4 + lane - 4] = sigmoidf_(w) * 9.5f + 0.5f;
    }
}

// ---------------- local window attention ----------------
#define HSTRIDE 65
__global__ void __launch_bounds__(256) attn_kernel()
{
    extern __shared__ float sm[];
    float* k_s = sm;
    float* v_s = sm + 196 * HSTRIDE;
    float* q_s = v_s + 196 * HSTRIDE;

    int tile = blockIdx.x;
    int b = blockIdx.y;
    int h = blockIdx.z;
    int ty0 = (tile >> 3) * 8, tx0 = (tile & 7) * 8;
    int tid = threadIdx.x;

    for (int idx = tid; idx < 196 * 16; idx += 256) {
        int r = idx >> 4;
        int c4 = (idx & 15) * 4;
        int hy = ty0 + (r / 14) - 3;
        int hx = tx0 + (r % 14) - 3;
        float4 kq = make_float4(0.f, 0.f, 0.f, 0.f);
        float4 vq = make_float4(0.f, 0.f, 0.f, 0.f);
        if (hy >= 0 && hy < 64 && hx >= 0 && hx < 64) {
            int tokg = b * 4096 + hy * 64 + hx;
            kq = *(const float4*)&g_k[(size_t)tokg * CDIM + h * 64 + c4];
            vq = *(const float4*)&g_qkv[(size_t)tokg * QKVN + 512 + h * 64 + c4];
        }
        float* kd = &k_s[r * HSTRIDE + c4];
        kd[0] = kq.x; kd[1] = kq.y; kd[2] = kq.z; kd[3] = kq.w;
        float* vd = &v_s[r * HSTRIDE + c4];
        vd[0] = vq.x; vd[1] = vq.y; vd[2] = vq.z; vd[3] = vq.w;
    }
    for (int idx = tid; idx < 64 * 16; idx += 256) {
        int t = idx >> 4;
        int c4 = (idx & 15) * 4;
        int tokg = b * 4096 + (ty0 + (t >> 3)) * 64 + (tx0 + (t & 7));
        *(float4*)&q_s[t * 64 + c4] =
            *(const float4*)&g_q[(size_t)tokg * CDIM + h * 64 + c4];
    }
    __syncthreads();

    int warpId = tid >> 5, lane = tid & 31;
    int w1 = lane, w2 = lane + 32;
    bool has2 = (w2 < 49);
    int off1 = (w1 / 7) * 14 + (w1 % 7);
    int off2 = has2 ? (w2 / 7) * 14 + (w2 % 7) : 0;
    float di1 = (float)(w1 / 7 - 3), dj1 = (float)(w1 % 7 - 3);
    float rd1 = sqrtf(di1 * di1 + dj1 * dj1);
    float di2 = (float)(w2 / 7 - 3), dj2 = (float)(w2 % 7 - 3);
    float rd2 = sqrtf(di2 * di2 + dj2 * dj2);

    for (int t = 0; t < 8; t++) {
        int ly = warpId, lx = t;
        int base = ly * 14 + lx;
        const float* qp = &q_s[(warpId * 8 + t) * 64];
        const float* k1p = &k_s[(base + off1) * HSTRIDE];
        const float* k2p = &k_s[(base + off2) * HSTRIDE];
        float s1 = 0.f, s2 = 0.f;
#pragma unroll
        for (int d = 0; d < 64; d++) {
            float qd = qp[d];
            s1 += qd * k1p[d];
            s2 += qd * k2p[d];
        }
        int tokg = b * 4096 + (ty0 + ly) * 64 + (tx0 + lx);
        float width = g_width[tokg * NHEAD + h];
        float sharp = g_sharp[tokg * NHEAD + h];
        float m1 = s1 * 0.125f - (1.f - sigmoidf_((width - rd1) * sharp)) * 10000.f;
        float m2 = has2
                   ? s2 * 0.125f - (1.f - sigmoidf_((width - rd2) * sharp)) * 10000.f
                   : -1e30f;
        float mx = fmaxf(m1, m2);
#pragma unroll
        for (int off = 16; off >= 1; off >>= 1)
            mx = fmaxf(mx, __shfl_xor_sync(0xffffffffu, mx, off));
        float e1 = __expf(m1 - mx);
        float e2 = has2 ? __expf(m2 - mx) : 0.f;
        float ssum = e1 + e2;
#pragma unroll
        for (int off = 16; off >= 1; off >>= 1)
            ssum += __shfl_xor_sync(0xffffffffu, ssum, off);
        float inv = 1.f / ssum;
        float a1 = e1 * inv, a2 = e2 * inv;

        float o1 = 0.f, o2 = 0.f;
#pragma unroll
        for (int w = 0; w < 49; w++) {
            float a = (w < 32) ? __shfl_sync(0xffffffffu, a1, w)
                               : __shfl_sync(0xffffffffu, a2, w - 32);
            int vrow = base + (w / 7) * 14 + (w % 7);
            o1 += a * v_s[vrow * HSTRIDE + lane];
            o2 += a * v_s[vrow * HSTRIDE + lane + 32];
        }
        g_att[(size_t)tokg * CDIM + h * 64 + lane] = o1;
        g_att[(size_t)tokg * CDIM + h * 64 + lane + 32] = o2;
    }
}

// ---------------- per-token inverse rms of attention output ----------------
__global__ void __launch_bounds__(256) rmsinv_kernel()
{
    int lane = threadIdx.x & 31;
    int tok = blockIdx.x * 8 + (threadIdx.x >> 5);
    const float4* row = (const float4*)(g_att + (size_t)tok * CDIM);
    float s = 0.f;
#pragma unroll
    for (int i = 0; i < 2; i++) {
        float4 v = row[lane + i * 32];
        s += v.x * v.x + v.y * v.y + v.z * v.z + v.w * v.w;
    }
#pragma unroll
    for (int off = 16; off >= 1; off >>= 1) s += __shfl_xor_sync(0xffffffffu, s, off);
    if (lane == 0) g_rmsinv[tok] = rsqrtf(s * (1.f / 256.f) + 1e-6f);
}

// ---------------- launch ----------------
extern "C" void kernel_launch(void* const* d_in, const int* in_sizes, int n_in,
                              void* d_out, int out_size)
{
    const float* x       = (const float*)d_in[0];
    const float* W_qkv   = (const float*)d_in[1];
    const float* w_qnorm = (const float*)d_in[2];
    const float* w_knorm = (const float*)d_in[3];
    const float* W_wp    = (const float*)d_in[4];
    const float* b_wp    = (const float*)d_in[5];
    const float* w_onorm = (const float*)d_in[6];
    const float* W_out   = (const float*)d_in[7];
    const float* W_gate  = (const float*)d_in[8];
    const float* b_gate  = (const float*)d_in[9];
    float* out = (float*)d_out;

    float *p_qkv;
    __nv_bfloat16 *p_xs, *p_vs, *p_ms, *p_wqh, *p_wql, *p_wgh, *p_wgl, *p_woh, *p_wol;
    cudaGetSymbolAddress((void**)&p_qkv, g_qkv);
    cudaGetSymbolAddress((void**)&p_xs, g_xsplit);
    cudaGetSymbolAddress((void**)&p_vs, g_vsplit);
    cudaGetSymbolAddress((void**)&p_ms, g_msplit);
    cudaGetSymbolAddress((void**)&p_wqh, g_wqkv_hi);
    cudaGetSymbolAddress((void**)&p_wql, g_wqkv_lo);
    cudaGetSymbolAddress((void**)&p_wgh, g_wgate_hi);
    cudaGetSymbolAddress((void**)&p_wgl, g_wgate_lo);
    cudaGetSymbolAddress((void**)&p_woh, g_wout_hi);
    cudaGetSymbolAddress((void**)&p_wol, g_wout_lo);

    // 0) split x and weights to bf16 hi/lo
    split_x_kernel<<<2048, 256>>>(x);
    split_w_kernel<<<320, 256>>>(W_qkv, W_gate, W_out);

    // 1) qkv = silu(x @ W_qkv)  (+ v split in epilogue)
    gemm_bf16<2><<<dim3(12, 64), 256>>>(p_xs, p_wqh, p_wql, 768,
                                        p_qkv, 768, nullptr, 0, nullptr, nullptr);

    // 2) rmsnorm + rope (q,k) + width/sharp projection
    norm_rope_wp<<<1024, 256>>>(x, W_wp, b_wp, w_qnorm, w_knorm);

    // 3) local attention
    size_t smem = (size_t)(196 * HSTRIDE * 2 + 64 * 64) * sizeof(float);
    cudaFuncSetAttribute(attn_kernel, cudaFuncAttributeMaxDynamicSharedMemorySize, (int)smem);
    attn_kernel<<<dim3(64, 2, 4), 256, smem>>>();

    // 4) per-token rms of attention output
    rmsinv_kernel<<<1024, 256>>>();

    // 5) gate GEMM + fused rmsnorm-scale + gate-merge (-> merged split)
    gemm_bf16<1><<<dim3(4, 64), 256>>>(p_vs, p_wgh, p_wgl, 256,
                                       nullptr, 0, p_qkv + 512, 768, b_gate, w_onorm);

    // 6) out = silu(merged @ W_out)
    gemm_bf16<0><<<dim3(4, 64), 256>>>(p_ms, p_woh, p_wol, 256,
                                       out, 256, nullptr, 0, nullptr, nullptr);
}

// round 6
// speedup vs baseline: 1.4508x; 1.4508x over previous
#include <cuda_runtime.h>
#include <cuda_bf16.h>
#include <mma.h>
#include <math.h>

using namespace nvcuda;

#define NTOK 8192
#define CDIM 256
#define NHEAD 4
#define QKVN 768
#define MAXDIST 4.242640687119285f  /* sqrt(18) */

// ---------------- scratch ----------------
__device__ float g_qkv[NTOK * QKVN];      // silu(x@W_qkv)  (q|k|v)
__device__ float g_q[NTOK * CDIM];
__device__ float g_k[NTOK * CDIM];
__device__ float g_att[NTOK * CDIM];
__device__ float g_merged[NTOK * CDIM];
__device__ float g_width[NTOK * NHEAD];
__device__ float g_sharp[NTOK * NHEAD];
__device__ float g_rmsinv[NTOK];
__device__ float g_wpT[8 * 256];          // W_wp transposed [o][c]

__device__ __forceinline__ float sigmoidf_(float x) { return 1.f / (1.f + __expf(-x)); }
__device__ __forceinline__ float siluf_(float x) { return x * sigmoidf_(x); }

__device__ __forceinline__ void split_bf16(float f, __nv_bfloat16& hi, __nv_bfloat16& lo) {
    hi = __float2bfloat16(f);
    lo = __float2bfloat16(f - __bfloat162float(hi));
}

// ---------------- tensor-core GEMM: 128x64 block tile, split-bf16 (3 HMMA) ----------------
// (known-good R2 version: 276 us total)
#define A_LD 40
#define B_LD 72
#define C_LD 36

template <int EPI>
__global__ void __launch_bounds__(256) gemm_mma(
    const float* __restrict__ A, int lda,
    const float* __restrict__ B, int ldb,
    float* __restrict__ Cmat, int ldc,
    const float* __restrict__ bias,
    const float* __restrict__ wonorm)
{
    __shared__ __align__(16) unsigned char smraw[36992];
    __nv_bfloat16 (*As)[128][A_LD] = (__nv_bfloat16(*)[128][A_LD])smraw;            // [2][128][40]
    __nv_bfloat16 (*Bs)[32][B_LD]  = (__nv_bfloat16(*)[32][B_LD])(smraw + 2 * 128 * A_LD * 2);
    float (*Cs)[32][C_LD]          = (float(*)[32][C_LD])smraw;

    int tid = threadIdx.x;
    int warp = tid >> 5, lane = tid & 31;
    int wm = warp >> 1, wn = warp & 1;
    int rowBase = blockIdx.y * 128;
    int colBase = blockIdx.x * 64;

    wmma::fragment<wmma::accumulator, 16, 16, 16, float> cf[2][2];
#pragma unroll
    for (int i = 0; i < 2; i++)
#pragma unroll
        for (int j = 0; j < 2; j++) wmma::fill_fragment(cf[i][j], 0.f);

    int ar = tid >> 3, ac4 = (tid & 7) * 4;

    for (int kt = 0; kt < 256; kt += 32) {
        float4 av[4], bv[2];
#pragma unroll
        for (int p = 0; p < 4; p++)
            av[p] = *(const float4*)(A + (size_t)(rowBase + ar + p * 32) * lda + kt + ac4);
#pragma unroll
        for (int p = 0; p < 2; p++) {
            int idx = tid + p * 256;
            bv[p] = *(const float4*)(B + (size_t)(kt + (idx >> 4)) * ldb + colBase + (idx & 15) * 4);
        }
        __syncthreads();
#pragma unroll
        for (int p = 0; p < 4; p++) {
            int r = ar + p * 32;
            float e[4] = {av[p].x, av[p].y, av[p].z, av[p].w};
#pragma unroll
            for (int q = 0; q < 4; q++) {
                __nv_bfloat16 hi, lo;
                split_bf16(e[q], hi, lo);
                As[0][r][ac4 + q] = hi;
                As[1][r][ac4 + q] = lo;
            }
        }
#pragma unroll
        for (int p = 0; p < 2; p++) {
            int idx = tid + p * 256;
            int r = idx >> 4, c4 = (idx & 15) * 4;
            float e[4] = {bv[p].x, bv[p].y, bv[p].z, bv[p].w};
#pragma unroll
            for (int q = 0; q < 4; q++) {
                __nv_bfloat16 hi, lo;
                split_bf16(e[q], hi, lo);
                Bs[0][r][c4 + q] = hi;
                Bs[1][r][c4 + q] = lo;
            }
        }
        __syncthreads();

#pragma unroll
        for (int ks = 0; ks < 32; ks += 16) {
            wmma::fragment<wmma::matrix_a, 16, 16, 16, __nv_bfloat16, wmma::row_major> ah[2], al[2];
            wmma::fragment<wmma::matrix_b, 16, 16, 16, __nv_bfloat16, wmma::row_major> bh[2], bl[2];
#pragma unroll
            for (int i = 0; i < 2; i++) {
                wmma::load_matrix_sync(ah[i], &As[0][wm * 32 + i * 16][ks], A_LD);
                wmma::load_matrix_sync(al[i], &As[1][wm * 32 + i * 16][ks], A_LD);
            }
#pragma unroll
            for (int j = 0; j < 2; j++) {
                wmma::load_matrix_sync(bh[j], &Bs[0][ks][wn * 32 + j * 16], B_LD);
                wmma::load_matrix_sync(bl[j], &Bs[1][ks][wn * 32 + j * 16], B_LD);
            }
#pragma unroll
            for (int i = 0; i < 2; i++)
#pragma unroll
                for (int j = 0; j < 2; j++) {
                    wmma::mma_sync(cf[i][j], ah[i], bh[j], cf[i][j]);
                    wmma::mma_sync(cf[i][j], ah[i], bl[j], cf[i][j]);
                    wmma::mma_sync(cf[i][j], al[i], bh[j], cf[i][j]);
                }
        }
    }

    __syncthreads();
#pragma unroll
    for (int i = 0; i < 2; i++)
#pragma unroll
        for (int j = 0; j < 2; j++)
            wmma::store_matrix_sync(&Cs[warp][i * 16][j * 16], cf[i][j], C_LD, wmma::mem_row_major);
    __syncwarp();

#pragma unroll 4
    for (int rr = 0; rr < 32; rr++) {
        int r = rowBase + wm * 32 + rr;
        int c = colBase + wn * 32 + lane;
        float val = Cs[warp][rr][lane];
        if (EPI == 0) {
            Cmat[(size_t)r * ldc + c] = siluf_(val);
        } else {
            float t = val + bias[c];
            float g = sigmoidf_(siluf_(t));
            float vv = A[(size_t)r * lda + c];
            float att = g_att[(size_t)r * CDIM + c] * g_rmsinv[r] * wonorm[c];
            Cmat[(size_t)r * ldc + c] = g * vv + (1.f - g) * att;
        }
    }
}

// ---------------- transpose W_wp -> [8][256] ----------------
__global__ void transpose_wp(const float* __restrict__ Wwp)
{
    int c = threadIdx.x;    // 256 threads
#pragma unroll
    for (int o = 0; o < 8; o++)
        g_wpT[o * 256 + c] = Wwp[c * 8 + o];
}

// ---------------- fused rmsnorm + RoPE (pos = head index!) + width/sharp ----------------
// warp per token; lane l holds channels [l*8, l*8+8); all loads float4-coalesced.
__global__ void __launch_bounds__(256) norm_rope_wp(
    const float* __restrict__ x,
    const float* __restrict__ bwp,
    const float* __restrict__ wqn, const float* __restrict__ wkn)
{
    int lane = threadIdx.x & 31;
    int tok = blockIdx.x * 8 + (threadIdx.x >> 5);
    const float4* row = (const float4*)(g_qkv + (size_t)tok * QKVN);

    float qv[8], kv[8];
    {
        float4 q0 = row[lane * 2], q1 = row[lane * 2 + 1];
        float4 k0 = row[64 + lane * 2], k1 = row[64 + lane * 2 + 1];
        qv[0] = q0.x; qv[1] = q0.y; qv[2] = q0.z; qv[3] = q0.w;
        qv[4] = q1.x; qv[5] = q1.y; qv[6] = q1.z; qv[7] = q1.w;
        kv[0] = k0.x; kv[1] = k0.y; kv[2] = k0.z; kv[3] = k0.w;
        kv[4] = k1.x; kv[5] = k1.y; kv[6] = k1.z; kv[7] = k1.w;
    }
    float sq = 0.f, sk = 0.f;
#pragma unroll
    for (int e = 0; e < 8; e++) { sq += qv[e] * qv[e]; sk += kv[e] * kv[e]; }
#pragma unroll
    for (int off = 1; off < 8; off <<= 1) {
        sq += __shfl_xor_sync(0xffffffffu, sq, off);
        sk += __shfl_xor_sync(0xffffffffu, sk, off);
    }
    float rq = rsqrtf(sq * (1.f / 64.f) + 1e-6f);
    float rk = rsqrtf(sk * (1.f / 64.f) + 1e-6f);

    int h = lane >> 3;     // head index = RoPE position
    int dl = lane & 7;
#pragma unroll
    for (int e = 0; e < 8; e++) {
        int d = dl * 8 + e;
        qv[e] *= rq * wqn[d];
        kv[e] *= rk * wkn[d];
    }
    float sgn = (lane & 4) ? 1.f : -1.f;
#pragma unroll
    for (int e = 0; e < 8; e++) {
        float qp = __shfl_xor_sync(0xffffffffu, qv[e], 4);
        float kp = __shfl_xor_sync(0xffffffffu, kv[e], 4);
        int f = (lane & 3) * 8 + e;
        float freq = exp2f(-(float)f * (13.287712379549449f / 32.f));
        float ang = (float)h * freq;
        float ss, cc;
        __sincosf(ang, &ss, &cc);
        qv[e] = qv[e] * cc + sgn * qp * ss;
        kv[e] = kv[e] * cc + sgn * kp * ss;
    }
    {
        float4* qo = (float4*)(g_q + (size_t)tok * CDIM);
        float4* ko = (float4*)(g_k + (size_t)tok * CDIM);
        qo[lane * 2]     = make_float4(qv[0], qv[1], qv[2], qv[3]);
        qo[lane * 2 + 1] = make_float4(qv[4], qv[5], qv[6], qv[7]);
        ko[lane * 2]     = make_float4(kv[0], kv[1], kv[2], kv[3]);
        ko[lane * 2 + 1] = make_float4(kv[4], kv[5], kv[6], kv[7]);
    }

    // width/sharpness: wp = silu(x@W_wp + b), 8 outputs via transposed coalesced W
    const float4* xr4 = (const float4*)(x + (size_t)tok * CDIM);
    float4 x0 = xr4[lane * 2], x1 = xr4[lane * 2 + 1];
    float keep = 0.f;
#pragma unroll
    for (int o = 0; o < 8; o++) {
        const float4* wr = (const float4*)(g_wpT + o * 256);
        float4 w0 = wr[lane * 2], w1 = wr[lane * 2 + 1];
        float p = x0.x * w0.x + x0.y * w0.y + x0.z * w0.z + x0.w * w0.w
                + x1.x * w1.x + x1.y * w1.y + x1.z * w1.z + x1.w * w1.w;
#pragma unroll
        for (int off = 16; off >= 1; off >>= 1) p += __shfl_xor_sync(0xffffffffu, p, off);
        if (lane == o) keep = p;
    }
    if (lane < 8) {
        float w = siluf_(keep + bwp[lane]);
        if (lane < 4) g_width[tok * 4 + lane] = sigmoidf_(w) * MAXDIST + 0.5f;
        else          g_sharp[tok * 4 + lane - 4] = sigmoidf_(w) * 9.5f + 0.5f;
    }
}

// ---------------- local window attention ----------------
#define HSTRIDE 65
__global__ void __launch_bounds__(256) attn_kernel()
{
    extern __shared__ float sm[];
    float* k_s = sm;
    float* v_s = sm + 196 * HSTRIDE;
    float* q_s = v_s + 196 * HSTRIDE;

    int tile = blockIdx.x;
    int b = blockIdx.y;
    int h = blockIdx.z;
    int ty0 = (tile >> 3) * 8, tx0 = (tile & 7) * 8;
    int tid = threadIdx.x;

    for (int idx = tid; idx < 196 * 16; idx += 256) {
        int r = idx >> 4;
        int c4 = (idx & 15) * 4;
        int hy = ty0 + (r / 14) - 3;
        int hx = tx0 + (r % 14) - 3;
        float4 kq = make_float4(0.f, 0.f, 0.f, 0.f);
        float4 vq = make_float4(0.f, 0.f, 0.f, 0.f);
        if (hy >= 0 && hy < 64 && hx >= 0 && hx < 64) {
            int tokg = b * 4096 + hy * 64 + hx;
            kq = *(const float4*)&g_k[(size_t)tokg * CDIM + h * 64 + c4];
            vq = *(const float4*)&g_qkv[(size_t)tokg * QKVN + 512 + h * 64 + c4];
        }
        float* kd = &k_s[r * HSTRIDE + c4];
        kd[0] = kq.x; kd[1] = kq.y; kd[2] = kq.z; kd[3] = kq.w;
        float* vd = &v_s[r * HSTRIDE + c4];
        vd[0] = vq.x; vd[1] = vq.y; vd[2] = vq.z; vd[3] = vq.w;
    }
    for (int idx = tid; idx < 64 * 16; idx += 256) {
        int t = idx >> 4;
        int c4 = (idx & 15) * 4;
        int tokg = b * 4096 + (ty0 + (t >> 3)) * 64 + (tx0 + (t & 7));
        *(float4*)&q_s[t * 64 + c4] =
            *(const float4*)&g_q[(size_t)tokg * CDIM + h * 64 + c4];
    }
    __syncthreads();

    int warpId = tid >> 5, lane = tid & 31;
    int w1 = lane, w2 = lane + 32;
    bool has2 = (w2 < 49);
    int off1 = (w1 / 7) * 14 + (w1 % 7);
    int off2 = has2 ? (w2 / 7) * 14 + (w2 % 7) : 0;
    float di1 = (float)(w1 / 7 - 3), dj1 = (float)(w1 % 7 - 3);
    float rd1 = sqrtf(di1 * di1 + dj1 * dj1);
    float di2 = (float)(w2 / 7 - 3), dj2 = (float)(w2 % 7 - 3);
    float rd2 = sqrtf(di2 * di2 + dj2 * dj2);

    for (int t = 0; t < 8; t++) {
        int ly = warpId, lx = t;
        int base = ly * 14 + lx;
        const float* qp = &q_s[(warpId * 8 + t) * 64];
        const float* k1p = &k_s[(base + off1) * HSTRIDE];
        const float* k2p = &k_s[(base + off2) * HSTRIDE];
        float s1 = 0.f, s2 = 0.f;
#pragma unroll
        for (int d = 0; d < 64; d++) {
            float qd = qp[d];
            s1 += qd * k1p[d];
            s2 += qd * k2p[d];
        }
        int tokg = b * 4096 + (ty0 + ly) * 64 + (tx0 + lx);
        float width = g_width[tokg * NHEAD + h];
        float sharp = g_sharp[tokg * NHEAD + h];
        float m1 = s1 * 0.125f - (1.f - sigmoidf_((width - rd1) * sharp)) * 10000.f;
        float m2 = has2
                   ? s2 * 0.125f - (1.f - sigmoidf_((width - rd2) * sharp)) * 10000.f
                   : -1e30f;
        float mx = fmaxf(m1, m2);
#pragma unroll
        for (int off = 16; off >= 1; off >>= 1)
            mx = fmaxf(mx, __shfl_xor_sync(0xffffffffu, mx, off));
        float e1 = __expf(m1 - mx);
        float e2 = has2 ? __expf(m2 - mx) : 0.f;
        float ssum = e1 + e2;
#pragma unroll
        for (int off = 16; off >= 1; off >>= 1)
            ssum += __shfl_xor_sync(0xffffffffu, ssum, off);
        float inv = 1.f / ssum;
        float a1 = e1 * inv, a2 = e2 * inv;

        float o1 = 0.f, o2 = 0.f;
#pragma unroll
        for (int w = 0; w < 49; w++) {
            float a = (w < 32) ? __shfl_sync(0xffffffffu, a1, w)
                               : __shfl_sync(0xffffffffu, a2, w - 32);
            int vrow = base + (w / 7) * 14 + (w % 7);
            o1 += a * v_s[vrow * HSTRIDE + lane];
            o2 += a * v_s[vrow * HSTRIDE + lane + 32];
        }
        g_att[(size_t)tokg * CDIM + h * 64 + lane] = o1;
        g_att[(size_t)tokg * CDIM + h * 64 + lane + 32] = o2;
    }
}

// ---------------- per-token inverse rms of attention output ----------------
__global__ void __launch_bounds__(256) rmsinv_kernel()
{
    int lane = threadIdx.x & 31;
    int tok = blockIdx.x * 8 + (threadIdx.x >> 5);
    const float4* row = (const float4*)(g_att + (size_t)tok * CDIM);
    float s = 0.f;
#pragma unroll
    for (int i = 0; i < 2; i++) {
        float4 v = row[lane + i * 32];
        s += v.x * v.x + v.y * v.y + v.z * v.z + v.w * v.w;
    }
#pragma unroll
    for (int off = 16; off >= 1; off >>= 1) s += __shfl_xor_sync(0xffffffffu, s, off);
    if (lane == 0) g_rmsinv[tok] = rsqrtf(s * (1.f / 256.f) + 1e-6f);
}

// ---------------- launch ----------------
extern "C" void kernel_launch(void* const* d_in, const int* in_sizes, int n_in,
                              void* d_out, int out_size)
{
    const float* x       = (const float*)d_in[0];
    const float* W_qkv   = (const float*)d_in[1];
    const float* w_qnorm = (const float*)d_in[2];
    const float* w_knorm = (const float*)d_in[3];
    const float* W_wp    = (const float*)d_in[4];
    const float* b_wp    = (const float*)d_in[5];
    const float* w_onorm = (const float*)d_in[6];
    const float* W_out   = (const float*)d_in[7];
    const float* W_gate  = (const float*)d_in[8];
    const float* b_gate  = (const float*)d_in[9];
    float* out = (float*)d_out;

    float *p_qkv, *p_merged;
    cudaGetSymbolAddress((void**)&p_qkv, g_qkv);
    cudaGetSymbolAddress((void**)&p_merged, g_merged);

    // 0) transpose W_wp
    transpose_wp<<<1, 256>>>(W_wp);

    // 1) qkv = silu(x @ W_qkv)
    gemm_mma<0><<<dim3(12, 64), 256>>>(x, 256, W_qkv, 768, p_qkv, 768, nullptr, nullptr);

    // 2) rmsnorm + rope (q,k) + width/sharp projection
    norm_rope_wp<<<1024, 256>>>(x, b_wp, w_qnorm, w_knorm);

    // 3) local attention
    size_t smem = (size_t)(196 * HSTRIDE * 2 + 64 * 64) * sizeof(float);
    cudaFuncSetAttribute(attn_kernel, cudaFuncAttributeMaxDynamicSharedMemorySize, (int)smem);
    attn_kernel<<<dim3(64, 2, 4), 256, smem>>>();

    // 4) per-token rms of attention output
    rmsinv_kernel<<<1024, 256>>>();

    // 5) gate GEMM + fused rmsnorm-scale + gate-merge
    gemm_mma<1><<<dim3(4, 64), 256>>>(p_qkv + 512, 768, W_gate, 256, p_merged, 256,
                                      b_gate, w_onorm);

    // 6) out = silu(merged @ W_out)
    gemm_mma<0><<<dim3(4, 64), 256>>>(p_merged, 256, W_out, 256, out, 256,
                                      nullptr, nullptr);
}